// round 3
// baseline (speedup 1.0000x reference)
#include <cuda_runtime.h>
#include <math.h>
#include <stdint.h>

#define T_TOK 32768
#define D_MOD 1024
#define N_EXP 64
#define CAP   1024
#define SELK  1032   // radix-select rank (margin 8 over CAP)
#define CAND  2048

// libdevice exp, immune to --use_fast_math remapping of expf
extern "C" __device__ float __nv_expf(float);
#define EXPF(v) __nv_expf(v)

// Scratch
__device__ float g_logits_t[N_EXP * T_TOK];  // transposed logits [E][T]
__device__ float g_max[N_EXP];
__device__ float g_sumA[N_EXP];              // mod-32 buckets + shfl tree
__device__ float g_sumB[N_EXP];              // mod-1024 buckets + smem tree

// ---------------------------------------------------------------------------
// Kernel 1: SGEMM logits = x @ W + b, split-K2 accumulation (bit-exact vs ref)
// Writes row-major (output 0) and transposed scratch.
// ---------------------------------------------------------------------------
__global__ __launch_bounds__(256) void gemm_kernel(
    const float* __restrict__ x, const float* __restrict__ W,
    const float* __restrict__ b, float* __restrict__ logits)
{
    __shared__ __align__(16) float As[16][64];
    __shared__ __align__(16) float Bs[16][64];

    const int m0  = blockIdx.x * 64;
    const int tid = threadIdx.x;
    const int tx  = tid & 15;
    const int ty  = tid >> 4;

    float acc[2][4][4];
#pragma unroll
    for (int r = 0; r < 2; r++)
#pragma unroll
        for (int i = 0; i < 4; i++)
#pragma unroll
            for (int j = 0; j < 4; j++) acc[r][i][j] = 0.0f;

    for (int k0 = 0; k0 < D_MOD; k0 += 16) {
#pragma unroll
        for (int i = tid; i < 64 * 16; i += 256) {
            int m = i >> 4, kk = i & 15;
            As[kk][m] = x[(size_t)(m0 + m) * D_MOD + k0 + kk];
        }
#pragma unroll
        for (int i = tid; i < 16 * 64; i += 256) {
            int kk = i >> 6, n = i & 63;
            Bs[kk][n] = W[(size_t)(k0 + kk) * N_EXP + n];
        }
        __syncthreads();

        const int half = (k0 < 512) ? 0 : 1;
        if (half == 0) {
#pragma unroll
            for (int kk = 0; kk < 16; kk++) {
                float4 av = *reinterpret_cast<const float4*>(&As[kk][ty * 4]);
                float4 bv = *reinterpret_cast<const float4*>(&Bs[kk][tx * 4]);
                float a[4] = {av.x, av.y, av.z, av.w};
                float bb[4] = {bv.x, bv.y, bv.z, bv.w};
#pragma unroll
                for (int i = 0; i < 4; i++)
#pragma unroll
                    for (int j = 0; j < 4; j++) acc[0][i][j] += a[i] * bb[j];
            }
        } else {
#pragma unroll
            for (int kk = 0; kk < 16; kk++) {
                float4 av = *reinterpret_cast<const float4*>(&As[kk][ty * 4]);
                float4 bv = *reinterpret_cast<const float4*>(&Bs[kk][tx * 4]);
                float a[4] = {av.x, av.y, av.z, av.w};
                float bb[4] = {bv.x, bv.y, bv.z, bv.w};
#pragma unroll
                for (int i = 0; i < 4; i++)
#pragma unroll
                    for (int j = 0; j < 4; j++) acc[1][i][j] += a[i] * bb[j];
            }
        }
        __syncthreads();
    }

#pragma unroll
    for (int i = 0; i < 4; i++) {
        int m = m0 + ty * 4 + i;
#pragma unroll
        for (int j = 0; j < 4; j++) {
            int n = tx * 4 + j;
            float v = (acc[0][i][j] + acc[1][i][j]) + b[n];
            logits[(size_t)m * N_EXP + n] = v;
            g_logits_t[(size_t)n * T_TOK + m] = v;
        }
    }
}

// ---------------------------------------------------------------------------
// Kernel 2: per-expert max (order-free)
// ---------------------------------------------------------------------------
__global__ __launch_bounds__(256) void max_kernel()
{
    const int e = blockIdx.x;
    const int tid = threadIdx.x;
    const float* col = g_logits_t + (size_t)e * T_TOK;
    __shared__ float sm[256];

    float m = -INFINITY;
    for (int i = tid; i < T_TOK; i += 256) m = fmaxf(m, col[i]);
    sm[tid] = m;
    __syncthreads();
    for (int s = 128; s > 0; s >>= 1) {
        if (tid < s) sm[tid] = fmaxf(sm[tid], sm[tid + s]);
        __syncthreads();
    }
    if (tid == 0) g_max[e] = sm[0];
}

// ---------------------------------------------------------------------------
// Kernel 3a: sumA — 32 buckets (t mod 32, ascending) + warp shfl tree
// One warp per expert.
// ---------------------------------------------------------------------------
__global__ __launch_bounds__(32) void sumA_kernel()
{
    const int e = blockIdx.x;
    const int lane = threadIdx.x;
    const float* col = g_logits_t + (size_t)e * T_TOK;
    const float mx = g_max[e];

    float acc = 0.0f;
    for (int j = 0; j < T_TOK / 32; j++)
        acc += EXPF(col[lane + 32 * j] - mx);
#pragma unroll
    for (int off = 16; off > 0; off >>= 1)
        acc += __shfl_xor_sync(0xFFFFFFFFu, acc, off);
    if (lane == 0) g_sumA[e] = acc;
}

// ---------------------------------------------------------------------------
// Kernel 3b: sumB — 1024 buckets (t mod 1024, ascending) + smem tree
// ---------------------------------------------------------------------------
__global__ __launch_bounds__(1024) void sumB_kernel()
{
    const int e = blockIdx.x;
    const int tid = threadIdx.x;
    const float* col = g_logits_t + (size_t)e * T_TOK;
    const float mx = g_max[e];
    __shared__ float sm[1024];

    float acc = 0.0f;
    for (int j = 0; j < T_TOK / 1024; j++)
        acc += EXPF(col[tid + 1024 * j] - mx);
    sm[tid] = acc;
    __syncthreads();
    for (int s = 512; s > 0; s >>= 1) {
        if (tid < s) sm[tid] += sm[tid + s];
        __syncthreads();
    }
    if (tid == 0) g_sumB[e] = sm[0];
}

// ---------------------------------------------------------------------------
// Kernel 4: probs (uses sumA)  — output 1 channel probes scheme A
// ---------------------------------------------------------------------------
__global__ __launch_bounds__(256) void probs_kernel(
    const float* __restrict__ logits, float* __restrict__ probs)
{
    int i = blockIdx.x * blockDim.x + threadIdx.x;
    if (i < T_TOK * N_EXP) {
        int e = i & (N_EXP - 1);
        probs[i] = __fdiv_rn(EXPF(logits[i] - g_max[e]), g_sumA[e]);
    }
}

// ---------------------------------------------------------------------------
// Kernel 5: per-expert top-1024 by PROB (uses sumB) — outputs 2/3 probe B.
// Radix-select rank SELK on logits (margin), candidates sorted by (p, ~idx).
// ---------------------------------------------------------------------------
__global__ __launch_bounds__(1024) void topk_kernel(
    float* __restrict__ out_vals, float* __restrict__ out_idx)
{
    extern __shared__ unsigned char smraw[];
    uint32_t* keys = reinterpret_cast<uint32_t*>(smraw);                   // 32768*4
    unsigned long long* cand =
        reinterpret_cast<unsigned long long*>(smraw + (size_t)T_TOK * 4);  // 2048*8

    __shared__ uint32_t hist[256];
    __shared__ uint32_t s_prefix, s_K, s_cnt;

    const int e = blockIdx.x;
    const int tid = threadIdx.x;
    const float* col = g_logits_t + (size_t)e * T_TOK;

    for (int i = tid; i < T_TOK; i += 1024) {
        uint32_t u = __float_as_uint(col[i]);
        keys[i] = (u & 0x80000000u) ? ~u : (u | 0x80000000u);
    }
    if (tid == 0) { s_prefix = 0u; s_K = SELK; }
    __syncthreads();

#pragma unroll
    for (int pass = 0; pass < 4; pass++) {
        const int shift = 24 - 8 * pass;
        const uint32_t maskhi = (pass == 0) ? 0u : (0xFFFFFFFFu << (shift + 8));
        if (tid < 256) hist[tid] = 0u;
        __syncthreads();
        const uint32_t pfx = s_prefix;
        for (int i = tid; i < T_TOK; i += 1024) {
            uint32_t key = keys[i];
            if ((key & maskhi) == pfx)
                atomicAdd(&hist[(key >> shift) & 0xFFu], 1u);
        }
        __syncthreads();
        if (tid == 0) {
            uint32_t cum = 0;
            for (int bin = 255; bin >= 0; bin--) {
                uint32_t c = hist[bin];
                if (cum + c >= s_K) {
                    s_K -= cum;
                    s_prefix |= ((uint32_t)bin) << shift;
                    break;
                }
                cum += c;
            }
        }
        __syncthreads();
    }
    const uint32_t V = s_prefix;

    if (tid == 0) s_cnt = 0u;
    __syncthreads();

    const float mx  = g_max[e];
    const float sum = g_sumB[e];

    for (int i = tid; i < T_TOK; i += 1024) {
        uint32_t key = keys[i];
        if (key >= V) {
            uint32_t u = (key & 0x80000000u) ? (key ^ 0x80000000u) : ~key;
            float l = __uint_as_float(u);
            float p = __fdiv_rn(EXPF(l - mx), sum);
            uint32_t pos = atomicAdd(&s_cnt, 1u);
            if (pos < CAND)
                cand[pos] = ((unsigned long long)__float_as_uint(p) << 32) |
                            (uint32_t)(~((uint32_t)i));
        }
    }
    __syncthreads();
    uint32_t n = s_cnt < CAND ? s_cnt : CAND;
    for (int i = tid; i < CAND; i += 1024)
        if ((uint32_t)i >= n) cand[i] = 0ull;
    __syncthreads();

    for (int ksz = 2; ksz <= CAND; ksz <<= 1) {
        for (int j = ksz >> 1; j > 0; j >>= 1) {
            for (int i = tid; i < CAND; i += 1024) {
                int ixj = i ^ j;
                if (ixj > i) {
                    unsigned long long a = cand[i];
                    unsigned long long c = cand[ixj];
                    bool up = ((i & ksz) == 0);
                    if ((a < c) == up) { cand[i] = c; cand[ixj] = a; }
                }
            }
            __syncthreads();
        }
    }

    {
        unsigned long long c = cand[tid];
        out_vals[(size_t)e * CAP + tid] = __uint_as_float((uint32_t)(c >> 32));
        out_idx [(size_t)e * CAP + tid] = (float)(~((uint32_t)(c & 0xFFFFFFFFull)));
    }
}

// ---------------------------------------------------------------------------
extern "C" void kernel_launch(void* const* d_in, const int* in_sizes, int n_in,
                              void* d_out, int out_size)
{
    const float* x = (const float*)d_in[0];
    const float* W = (const float*)d_in[1];
    const float* b = (const float*)d_in[2];

    float* out    = (float*)d_out;
    float* logits = out;                                 // [T,E]
    float* probs  = out + (size_t)T_TOK * N_EXP;         // [T,E]
    float* evals  = out + 2 * (size_t)T_TOK * N_EXP;     // [E,CAP]
    float* eidx   = evals + (size_t)N_EXP * CAP;         // [E,CAP]

    size_t topk_smem = (size_t)T_TOK * 4 + (size_t)CAND * 8;
    cudaFuncSetAttribute(topk_kernel,
                         cudaFuncAttributeMaxDynamicSharedMemorySize,
                         (int)topk_smem);

    gemm_kernel<<<T_TOK / 64, 256>>>(x, W, b, logits);
    max_kernel<<<N_EXP, 256>>>();
    sumA_kernel<<<N_EXP, 32>>>();
    sumB_kernel<<<N_EXP, 1024>>>();
    probs_kernel<<<(T_TOK * N_EXP + 255) / 256, 256>>>(logits, probs);
    topk_kernel<<<N_EXP, 1024, topk_smem>>>(evals, eidx);
}

// round 4
// speedup vs baseline: 1.2733x; 1.2733x over previous
#include <cuda_runtime.h>
#include <math.h>
#include <stdint.h>

#define T_TOK 32768
#define D_MOD 1024
#define N_EXP 64
#define CAP   1024
#define SELK  1032   // radix-select rank (margin over CAP)
#define CAND  2048

typedef unsigned long long u64;

// libdevice exp, immune to fast-math remap
extern "C" __device__ float __nv_expf(float);
#define EXPF(v) __nv_expf(v)

// Scratch
__device__ float g_logits_t[N_EXP * T_TOK];  // transposed logits [E][T]
__device__ float g_max[N_EXP];
__device__ float g_sum[N_EXP];

// ---------------- f32x2 helpers ----------------
__device__ __forceinline__ u64 pack_dup(float v) {
    u64 d; asm("mov.b64 %0, {%1, %1};" : "=l"(d) : "f"(v)); return d;
}
__device__ __forceinline__ void fma2(u64& d, u64 a, u64 b) {
    asm("fma.rn.f32x2 %0, %1, %2, %0;" : "+l"(d) : "l"(a), "l"(b));
}
__device__ __forceinline__ u64 add2(u64 a, u64 b) {
    u64 d; asm("add.rn.f32x2 %0, %1, %2;" : "=l"(d) : "l"(a), "l"(b)); return d;
}
__device__ __forceinline__ void unpack2(u64 v, float& lo, float& hi) {
    asm("mov.b64 {%0, %1}, %2;" : "=f"(lo), "=f"(hi) : "l"(v));
}
__device__ __forceinline__ void lds_v2u64(uint32_t addr, u64& a, u64& b) {
    asm volatile("ld.shared.v2.u64 {%0, %1}, [%2];"
                 : "=l"(a), "=l"(b) : "r"(addr));
}

// ---------------------------------------------------------------------------
// Kernel 1: SGEMM logits = x @ W + b, split-K2 (bit-exact), FFMA2 inner loop.
// Block tile 128m x 64n, 256 threads, thread tile 8m x 4n (m packed in pairs).
// ---------------------------------------------------------------------------
#define BM   128
#define KT   16
#define ASTR 132   // As row stride in floats (132*4=528B: 16B-aligned rows)

__global__ __launch_bounds__(256, 2) void gemm_kernel(
    const float* __restrict__ x, const float* __restrict__ W,
    const float* __restrict__ bias, float* __restrict__ logits)
{
    __shared__ __align__(16) float As[KT][ASTR];   // [kk][m]
    __shared__ __align__(16) u64   Bs[KT][N_EXP];  // duplicated (w,w) pairs

    const int tid = threadIdx.x;
    const int tx  = tid & 15;   // n-group (4 experts)
    const int ty  = tid >> 4;   // m-group (8 tokens)
    const int m0  = blockIdx.x * BM;

    // global-load mapping
    const int am  = tid >> 2;   // 0..63 (second load adds +64)
    const int akg = tid & 3;    // k-group of 4
    const int wkk = tid >> 4;   // 0..15
    const int wng = tid & 15;   // n-group of 4

    u64 bias2[4];
#pragma unroll
    for (int n = 0; n < 4; n++) bias2[n] = pack_dup(bias[tx * 4 + n]);

    u64 acc[2][4][4];   // [half][m-pair][n]
#pragma unroll
    for (int h = 0; h < 2; h++)
#pragma unroll
        for (int mp = 0; mp < 4; mp++)
#pragma unroll
            for (int n = 0; n < 4; n++) acc[h][mp][n] = 0ull;

    const uint32_t aBase = (uint32_t)__cvta_generic_to_shared(&As[0][0]);
    const uint32_t bBase = (uint32_t)__cvta_generic_to_shared(&Bs[0][0]);
    const uint32_t aRow  = aBase + (uint32_t)(ty * 8) * 4u;
    const uint32_t bRow  = bBase + (uint32_t)(tx * 4) * 8u;

    // prefetch tile 0
    float4 xa0 = *(const float4*)&x[(size_t)(m0 + am) * D_MOD + akg * 4];
    float4 xa1 = *(const float4*)&x[(size_t)(m0 + am + 64) * D_MOD + akg * 4];
    float4 wv  = *(const float4*)&W[(size_t)wkk * N_EXP + wng * 4];

#define COMPUTE(H)                                                          \
    _Pragma("unroll")                                                       \
    for (int kk = 0; kk < KT; kk++) {                                       \
        u64 a0, a1, a2, a3, b0, b1, b2, b3;                                 \
        uint32_t ar = aRow + (uint32_t)(kk * ASTR) * 4u;                    \
        lds_v2u64(ar,      a0, a1);                                         \
        lds_v2u64(ar + 16, a2, a3);                                         \
        uint32_t br = bRow + (uint32_t)(kk * N_EXP) * 8u;                   \
        lds_v2u64(br,      b0, b1);                                         \
        lds_v2u64(br + 16, b2, b3);                                         \
        fma2(acc[H][0][0], a0, b0); fma2(acc[H][0][1], a0, b1);             \
        fma2(acc[H][0][2], a0, b2); fma2(acc[H][0][3], a0, b3);             \
        fma2(acc[H][1][0], a1, b0); fma2(acc[H][1][1], a1, b1);             \
        fma2(acc[H][1][2], a1, b2); fma2(acc[H][1][3], a1, b3);             \
        fma2(acc[H][2][0], a2, b0); fma2(acc[H][2][1], a2, b1);             \
        fma2(acc[H][2][2], a2, b2); fma2(acc[H][2][3], a2, b3);             \
        fma2(acc[H][3][0], a3, b0); fma2(acc[H][3][1], a3, b1);             \
        fma2(acc[H][3][2], a3, b2); fma2(acc[H][3][3], a3, b3);             \
    }

    for (int t = 0; t < D_MOD / KT; t++) {
        // stage prefetched tile into smem
        As[akg * 4 + 0][am] = xa0.x;  As[akg * 4 + 1][am] = xa0.y;
        As[akg * 4 + 2][am] = xa0.z;  As[akg * 4 + 3][am] = xa0.w;
        As[akg * 4 + 0][am + 64] = xa1.x;  As[akg * 4 + 1][am + 64] = xa1.y;
        As[akg * 4 + 2][am + 64] = xa1.z;  As[akg * 4 + 3][am + 64] = xa1.w;
        Bs[wkk][wng * 4 + 0] = pack_dup(wv.x);
        Bs[wkk][wng * 4 + 1] = pack_dup(wv.y);
        Bs[wkk][wng * 4 + 2] = pack_dup(wv.z);
        Bs[wkk][wng * 4 + 3] = pack_dup(wv.w);
        __syncthreads();

        if (t < D_MOD / KT - 1) {
            const int k0 = (t + 1) * KT;
            xa0 = *(const float4*)&x[(size_t)(m0 + am) * D_MOD + k0 + akg * 4];
            xa1 = *(const float4*)&x[(size_t)(m0 + am + 64) * D_MOD + k0 + akg * 4];
            wv  = *(const float4*)&W[(size_t)(k0 + wkk) * N_EXP + wng * 4];
        }

        if (t < 32) { COMPUTE(0) } else { COMPUTE(1) }
        __syncthreads();
    }

    // epilogue: v = (acc0 + acc1) + bias   (componentwise RN, bit-exact)
    float col[4][8];   // [n][m within thread tile]
#pragma unroll
    for (int mp = 0; mp < 4; mp++) {
        float r0[4], r1[4];
#pragma unroll
        for (int n = 0; n < 4; n++) {
            u64 s = add2(add2(acc[0][mp][n], acc[1][mp][n]), bias2[n]);
            unpack2(s, r0[n], r1[n]);
            col[n][mp * 2]     = r0[n];
            col[n][mp * 2 + 1] = r1[n];
        }
        const int m_lo = m0 + ty * 8 + mp * 2;
        *(float4*)&logits[(size_t)m_lo * N_EXP + tx * 4] =
            make_float4(r0[0], r0[1], r0[2], r0[3]);
        *(float4*)&logits[(size_t)(m_lo + 1) * N_EXP + tx * 4] =
            make_float4(r1[0], r1[1], r1[2], r1[3]);
    }
    // transposed copy, float4 along m
#pragma unroll
    for (int n = 0; n < 4; n++) {
        float* dst = &g_logits_t[(size_t)(tx * 4 + n) * T_TOK + m0 + ty * 8];
        *(float4*)&dst[0] = make_float4(col[n][0], col[n][1], col[n][2], col[n][3]);
        *(float4*)&dst[4] = make_float4(col[n][4], col[n][5], col[n][6], col[n][7]);
    }
}

// ---------------------------------------------------------------------------
// Kernel 2: fused per-expert softmax stats + exact top-1024.
// One 1024-thread block per expert; column cached in smem as ordered keys.
// ---------------------------------------------------------------------------
__global__ __launch_bounds__(1024) void topk_kernel(
    float* __restrict__ out_vals, float* __restrict__ out_idx)
{
    extern __shared__ unsigned char smraw[];
    uint32_t* keys = reinterpret_cast<uint32_t*>(smraw);                 // 32768*4
    u64* cand = reinterpret_cast<u64*>(smraw + (size_t)T_TOK * 4);       // 2048*8

    __shared__ uint32_t hist[256];
    __shared__ float red[1024];
    __shared__ uint32_t s_prefix, s_K, s_cnt, s_kmax;

    const int e = blockIdx.x;
    const int tid = threadIdx.x;
    const float* col = g_logits_t + (size_t)e * T_TOK;

    if (tid == 0) { s_prefix = 0u; s_K = SELK; s_cnt = 0u; s_kmax = 0u; }
    __syncthreads();

    // keyify + running max of ordered keys (key order == float order)
    uint32_t kmax = 0u;
    for (int ii = tid; ii < T_TOK / 4; ii += 1024) {
        float4 v = *(const float4*)&col[ii * 4];
        uint32_t u0 = __float_as_uint(v.x), u1 = __float_as_uint(v.y);
        uint32_t u2 = __float_as_uint(v.z), u3 = __float_as_uint(v.w);
        uint32_t k0 = (u0 & 0x80000000u) ? ~u0 : (u0 | 0x80000000u);
        uint32_t k1 = (u1 & 0x80000000u) ? ~u1 : (u1 | 0x80000000u);
        uint32_t k2 = (u2 & 0x80000000u) ? ~u2 : (u2 | 0x80000000u);
        uint32_t k3 = (u3 & 0x80000000u) ? ~u3 : (u3 | 0x80000000u);
        keys[ii * 4 + 0] = k0; keys[ii * 4 + 1] = k1;
        keys[ii * 4 + 2] = k2; keys[ii * 4 + 3] = k3;
        kmax = max(kmax, max(max(k0, k1), max(k2, k3)));
    }
#pragma unroll
    for (int off = 16; off > 0; off >>= 1)
        kmax = max(kmax, __shfl_xor_sync(0xFFFFFFFFu, kmax, off));
    if ((tid & 31) == 0) atomicMax(&s_kmax, kmax);
    __syncthreads();

    const uint32_t km = s_kmax;
    const float mx = __uint_as_float((km & 0x80000000u) ? (km ^ 0x80000000u) : ~km);

    // sum of exp(v - mx) (order-free: any sum works, division is monotone)
    float acc = 0.0f;
    for (int ii = tid; ii < T_TOK / 4; ii += 1024) {
        float4 v = *(const float4*)&col[ii * 4];
        acc += EXPF(v.x - mx) + EXPF(v.y - mx) + EXPF(v.z - mx) + EXPF(v.w - mx);
    }
    red[tid] = acc;
    __syncthreads();
    for (int s = 512; s > 0; s >>= 1) {
        if (tid < s) red[tid] += red[tid + s];
        __syncthreads();
    }
    const float sum = red[0];
    if (tid == 0) { g_max[e] = mx; g_sum[e] = sum; }
    __syncthreads();

    // 4-pass radix select for the SELK-th largest key
#pragma unroll
    for (int pass = 0; pass < 4; pass++) {
        const int shift = 24 - 8 * pass;
        const uint32_t maskhi = (pass == 0) ? 0u : (0xFFFFFFFFu << (shift + 8));
        if (tid < 256) hist[tid] = 0u;
        __syncthreads();
        const uint32_t pfx = s_prefix;
        for (int i = tid; i < T_TOK; i += 1024) {
            uint32_t key = keys[i];
            if ((key & maskhi) == pfx)
                atomicAdd(&hist[(key >> shift) & 0xFFu], 1u);
        }
        __syncthreads();
        if (tid == 0) {
            uint32_t cum = 0;
            for (int bin = 255; bin >= 0; bin--) {
                uint32_t c = hist[bin];
                if (cum + c >= s_K) {
                    s_K -= cum;
                    s_prefix |= ((uint32_t)bin) << shift;
                    break;
                }
                cum += c;
            }
        }
        __syncthreads();
    }
    const uint32_t V = s_prefix;

    // collect candidates, key = (prob, ~idx) composite (desc value, asc index)
    for (int i = tid; i < T_TOK; i += 1024) {
        uint32_t key = keys[i];
        if (key >= V) {
            uint32_t u = (key & 0x80000000u) ? (key ^ 0x80000000u) : ~key;
            float p = __fdiv_rn(EXPF(__uint_as_float(u) - mx), sum);
            uint32_t pos = atomicAdd(&s_cnt, 1u);
            if (pos < CAND)
                cand[pos] = ((u64)__float_as_uint(p) << 32) |
                            (uint32_t)(~((uint32_t)i));
        }
    }
    __syncthreads();
    uint32_t n = s_cnt < CAND ? s_cnt : CAND;
    for (int i = tid; i < CAND; i += 1024)
        if ((uint32_t)i >= n) cand[i] = 0ull;
    __syncthreads();

    // bitonic sort descending (2048 elements)
    for (int ksz = 2; ksz <= CAND; ksz <<= 1) {
        for (int j = ksz >> 1; j > 0; j >>= 1) {
            for (int i = tid; i < CAND; i += 1024) {
                int ixj = i ^ j;
                if (ixj > i) {
                    u64 a = cand[i];
                    u64 c = cand[ixj];
                    bool up = ((i & ksz) == 0);
                    if ((a < c) == up) { cand[i] = c; cand[ixj] = a; }
                }
            }
            __syncthreads();
        }
    }

    {
        u64 c = cand[tid];
        out_vals[(size_t)e * CAP + tid] = __uint_as_float((uint32_t)(c >> 32));
        out_idx [(size_t)e * CAP + tid] = (float)(~((uint32_t)(c & 0xFFFFFFFFull)));
    }
}

// ---------------------------------------------------------------------------
// Kernel 3: probs = exp(logits - max_e) / sum_e, float4 vectorized
// ---------------------------------------------------------------------------
__global__ __launch_bounds__(256) void probs_kernel(
    const float* __restrict__ logits, float* __restrict__ probs)
{
    const int i4 = (blockIdx.x * 256 + threadIdx.x) * 4;
    const int e0 = i4 & (N_EXP - 1);
    float4 v = *(const float4*)&logits[i4];
    float4 r;
    r.x = __fdiv_rn(EXPF(v.x - g_max[e0 + 0]), g_sum[e0 + 0]);
    r.y = __fdiv_rn(EXPF(v.y - g_max[e0 + 1]), g_sum[e0 + 1]);
    r.z = __fdiv_rn(EXPF(v.z - g_max[e0 + 2]), g_sum[e0 + 2]);
    r.w = __fdiv_rn(EXPF(v.w - g_max[e0 + 3]), g_sum[e0 + 3]);
    *(float4*)&probs[i4] = r;
}

// ---------------------------------------------------------------------------
extern "C" void kernel_launch(void* const* d_in, const int* in_sizes, int n_in,
                              void* d_out, int out_size)
{
    const float* x = (const float*)d_in[0];
    const float* W = (const float*)d_in[1];
    const float* b = (const float*)d_in[2];

    float* out    = (float*)d_out;
    float* logits = out;                                 // [T,E]
    float* probs  = out + (size_t)T_TOK * N_EXP;         // [T,E]
    float* evals  = out + 2 * (size_t)T_TOK * N_EXP;     // [E,CAP]
    float* eidx   = evals + (size_t)N_EXP * CAP;         // [E,CAP]

    size_t topk_smem = (size_t)T_TOK * 4 + (size_t)CAND * 8;
    cudaFuncSetAttribute(topk_kernel,
                         cudaFuncAttributeMaxDynamicSharedMemorySize,
                         (int)topk_smem);

    gemm_kernel<<<T_TOK / BM, 256>>>(x, W, b, logits);
    topk_kernel<<<N_EXP, 1024, topk_smem>>>(evals, eidx);
    probs_kernel<<<(T_TOK * N_EXP) / (256 * 4), 256>>>(logits, probs);
}

// round 5
// speedup vs baseline: 1.8467x; 1.4504x over previous
#include <cuda_runtime.h>
#include <math.h>
#include <stdint.h>

#define T_TOK 32768
#define D_MOD 1024
#define N_EXP 64
#define CAP   1024
#define SELK  1032
#define CAND  2048

typedef unsigned long long u64;

extern "C" __device__ float __nv_expf(float);
#define EXPF(v) __nv_expf(v)

// Scratch
__device__ float g_logits_t[N_EXP * T_TOK];
__device__ float g_max[N_EXP];
__device__ float g_sum[N_EXP];

// ---------------- f32x2 helpers ----------------
__device__ __forceinline__ u64 pack_dup(float v) {
    u64 d; asm("mov.b64 %0, {%1, %1};" : "=l"(d) : "f"(v)); return d;
}
__device__ __forceinline__ void fma2(u64& d, u64 a, u64 b) {
    asm("fma.rn.f32x2 %0, %1, %2, %0;" : "+l"(d) : "l"(a), "l"(b));
}
__device__ __forceinline__ u64 add2(u64 a, u64 b) {
    u64 d; asm("add.rn.f32x2 %0, %1, %2;" : "=l"(d) : "l"(a), "l"(b)); return d;
}
__device__ __forceinline__ void unpack2(u64 v, float& lo, float& hi) {
    asm("mov.b64 {%0, %1}, %2;" : "=f"(lo), "=f"(hi) : "l"(v));
}
__device__ __forceinline__ void lds_v2u64(uint32_t addr, u64& a, u64& b) {
    asm volatile("ld.shared.v2.u64 {%0, %1}, [%2];"
                 : "=l"(a), "=l"(b) : "r"(addr));
}

// ---------------------------------------------------------------------------
// Kernel 1: SGEMM logits = x @ W + b, split-K2 bit-exact, FFMA2.
// Block: 128 threads. Block tile 128m x 64n. Thread tile 8m(4 pairs) x 8n.
// Warp = 4 ty x 8 tx: A-loads 1 phase, B-loads (f32) 1 phase each.
// ---------------------------------------------------------------------------
#define BM   128
#define KT   16
#define ASTR 132

__global__ __launch_bounds__(128) void gemm_kernel(
    const float* __restrict__ x, const float* __restrict__ W,
    const float* __restrict__ bias, float* __restrict__ logits)
{
    __shared__ __align__(16) float As[KT][ASTR];   // [kk][m]
    __shared__ __align__(16) float Bs[KT][N_EXP];  // [kk][n] plain f32

    const int tid = threadIdx.x;
    const int tx  = tid & 7;     // n-group (8 experts)
    const int ty  = tid >> 3;    // m-group (8 tokens), 0..15
    const int m0  = blockIdx.x * BM;

    // global-load mapping
    const int am  = tid >> 2;    // 0..31 (+32p for 4 passes)
    const int akg = tid & 3;     // k-group of 4 floats
    const int wkk = tid >> 3;    // 0..15
    const int wng = tid & 7;     // n-group of 8 floats

    u64 acc[2][4][8];
#pragma unroll
    for (int h = 0; h < 2; h++)
#pragma unroll
        for (int mp = 0; mp < 4; mp++)
#pragma unroll
            for (int n = 0; n < 8; n++) acc[h][mp][n] = 0ull;

    const uint32_t aBase = (uint32_t)__cvta_generic_to_shared(&As[0][0]);
    const uint32_t aRow  = aBase + (uint32_t)(ty * 8) * 4u;

    // prefetch tile 0
    float4 xa[4];
#pragma unroll
    for (int p = 0; p < 4; p++)
        xa[p] = *(const float4*)&x[(size_t)(m0 + am + 32 * p) * D_MOD + akg * 4];
    float4 wv0 = *(const float4*)&W[(size_t)wkk * N_EXP + wng * 8];
    float4 wv1 = *(const float4*)&W[(size_t)wkk * N_EXP + wng * 8 + 4];

#define COMPUTE(H)                                                           \
    _Pragma("unroll")                                                        \
    for (int kk = 0; kk < KT; kk++) {                                        \
        u64 a0, a1, a2, a3;                                                  \
        uint32_t ar = aRow + (uint32_t)(kk * ASTR) * 4u;                     \
        lds_v2u64(ar,      a0, a1);                                          \
        lds_v2u64(ar + 16, a2, a3);                                          \
        float4 bv0 = *(const float4*)&Bs[kk][tx * 8];                        \
        float4 bv1 = *(const float4*)&Bs[kk][tx * 8 + 4];                    \
        u64 b0 = pack_dup(bv0.x), b1 = pack_dup(bv0.y);                      \
        u64 b2 = pack_dup(bv0.z), b3 = pack_dup(bv0.w);                      \
        u64 b4 = pack_dup(bv1.x), b5 = pack_dup(bv1.y);                      \
        u64 b6 = pack_dup(bv1.z), b7 = pack_dup(bv1.w);                      \
        fma2(acc[H][0][0], a0, b0); fma2(acc[H][0][1], a0, b1);              \
        fma2(acc[H][0][2], a0, b2); fma2(acc[H][0][3], a0, b3);              \
        fma2(acc[H][0][4], a0, b4); fma2(acc[H][0][5], a0, b5);              \
        fma2(acc[H][0][6], a0, b6); fma2(acc[H][0][7], a0, b7);              \
        fma2(acc[H][1][0], a1, b0); fma2(acc[H][1][1], a1, b1);              \
        fma2(acc[H][1][2], a1, b2); fma2(acc[H][1][3], a1, b3);              \
        fma2(acc[H][1][4], a1, b4); fma2(acc[H][1][5], a1, b5);              \
        fma2(acc[H][1][6], a1, b6); fma2(acc[H][1][7], a1, b7);              \
        fma2(acc[H][2][0], a2, b0); fma2(acc[H][2][1], a2, b1);              \
        fma2(acc[H][2][2], a2, b2); fma2(acc[H][2][3], a2, b3);              \
        fma2(acc[H][2][4], a2, b4); fma2(acc[H][2][5], a2, b5);              \
        fma2(acc[H][2][6], a2, b6); fma2(acc[H][2][7], a2, b7);              \
        fma2(acc[H][3][0], a3, b0); fma2(acc[H][3][1], a3, b1);              \
        fma2(acc[H][3][2], a3, b2); fma2(acc[H][3][3], a3, b3);              \
        fma2(acc[H][3][4], a3, b4); fma2(acc[H][3][5], a3, b5);              \
        fma2(acc[H][3][6], a3, b6); fma2(acc[H][3][7], a3, b7);              \
    }

    for (int t = 0; t < D_MOD / KT; t++) {
#pragma unroll
        for (int p = 0; p < 4; p++) {
            As[akg * 4 + 0][am + 32 * p] = xa[p].x;
            As[akg * 4 + 1][am + 32 * p] = xa[p].y;
            As[akg * 4 + 2][am + 32 * p] = xa[p].z;
            As[akg * 4 + 3][am + 32 * p] = xa[p].w;
        }
        *(float4*)&Bs[wkk][wng * 8]     = wv0;
        *(float4*)&Bs[wkk][wng * 8 + 4] = wv1;
        __syncthreads();

        if (t < D_MOD / KT - 1) {
            const int k0 = (t + 1) * KT;
#pragma unroll
            for (int p = 0; p < 4; p++)
                xa[p] = *(const float4*)&x[(size_t)(m0 + am + 32 * p) * D_MOD + k0 + akg * 4];
            wv0 = *(const float4*)&W[(size_t)(k0 + wkk) * N_EXP + wng * 8];
            wv1 = *(const float4*)&W[(size_t)(k0 + wkk) * N_EXP + wng * 8 + 4];
        }

        if (t < 32) { COMPUTE(0) } else { COMPUTE(1) }
        __syncthreads();
    }

    // epilogue: (acc0 + acc1) + bias, componentwise RN (bit-exact split-K2)
    u64 bias2[8];
#pragma unroll
    for (int n = 0; n < 8; n++) bias2[n] = pack_dup(bias[tx * 8 + n]);

    float col[8][8];   // [n][m]
#pragma unroll
    for (int mp = 0; mp < 4; mp++) {
        float r0[8], r1[8];
#pragma unroll
        for (int n = 0; n < 8; n++) {
            u64 s = add2(add2(acc[0][mp][n], acc[1][mp][n]), bias2[n]);
            unpack2(s, r0[n], r1[n]);
            col[n][mp * 2]     = r0[n];
            col[n][mp * 2 + 1] = r1[n];
        }
        const int m_lo = m0 + ty * 8 + mp * 2;
        *(float4*)&logits[(size_t)m_lo * N_EXP + tx * 8] =
            make_float4(r0[0], r0[1], r0[2], r0[3]);
        *(float4*)&logits[(size_t)m_lo * N_EXP + tx * 8 + 4] =
            make_float4(r0[4], r0[5], r0[6], r0[7]);
        *(float4*)&logits[(size_t)(m_lo + 1) * N_EXP + tx * 8] =
            make_float4(r1[0], r1[1], r1[2], r1[3]);
        *(float4*)&logits[(size_t)(m_lo + 1) * N_EXP + tx * 8 + 4] =
            make_float4(r1[4], r1[5], r1[6], r1[7]);
    }
#pragma unroll
    for (int n = 0; n < 8; n++) {
        float* dst = &g_logits_t[(size_t)(tx * 8 + n) * T_TOK + m0 + ty * 8];
        *(float4*)&dst[0] = make_float4(col[n][0], col[n][1], col[n][2], col[n][3]);
        *(float4*)&dst[4] = make_float4(col[n][4], col[n][5], col[n][6], col[n][7]);
    }
}

// ---------------------------------------------------------------------------
// Kernel 2: fused softmax stats + exact top-1024 per expert
// ---------------------------------------------------------------------------
__global__ __launch_bounds__(1024) void topk_kernel(
    float* __restrict__ out_vals, float* __restrict__ out_idx)
{
    extern __shared__ unsigned char smraw[];
    uint32_t* keys = reinterpret_cast<uint32_t*>(smraw);
    u64* cand = reinterpret_cast<u64*>(smraw + (size_t)T_TOK * 4);

    __shared__ uint32_t hist[256];
    __shared__ float red[1024];
    __shared__ uint32_t s_prefix, s_K, s_cnt, s_kmax;

    const int e = blockIdx.x;
    const int tid = threadIdx.x;
    const float* col = g_logits_t + (size_t)e * T_TOK;

    if (tid == 0) { s_prefix = 0u; s_K = SELK; s_cnt = 0u; s_kmax = 0u; }
    __syncthreads();

    uint32_t kmax = 0u;
    for (int ii = tid; ii < T_TOK / 4; ii += 1024) {
        float4 v = *(const float4*)&col[ii * 4];
        uint32_t u0 = __float_as_uint(v.x), u1 = __float_as_uint(v.y);
        uint32_t u2 = __float_as_uint(v.z), u3 = __float_as_uint(v.w);
        uint32_t k0 = (u0 & 0x80000000u) ? ~u0 : (u0 | 0x80000000u);
        uint32_t k1 = (u1 & 0x80000000u) ? ~u1 : (u1 | 0x80000000u);
        uint32_t k2 = (u2 & 0x80000000u) ? ~u2 : (u2 | 0x80000000u);
        uint32_t k3 = (u3 & 0x80000000u) ? ~u3 : (u3 | 0x80000000u);
        keys[ii * 4 + 0] = k0; keys[ii * 4 + 1] = k1;
        keys[ii * 4 + 2] = k2; keys[ii * 4 + 3] = k3;
        kmax = max(kmax, max(max(k0, k1), max(k2, k3)));
    }
#pragma unroll
    for (int off = 16; off > 0; off >>= 1)
        kmax = max(kmax, __shfl_xor_sync(0xFFFFFFFFu, kmax, off));
    if ((tid & 31) == 0) atomicMax(&s_kmax, kmax);
    __syncthreads();

    const uint32_t km = s_kmax;
    const float mx = __uint_as_float((km & 0x80000000u) ? (km ^ 0x80000000u) : ~km);

    float acc = 0.0f;
    for (int ii = tid; ii < T_TOK / 4; ii += 1024) {
        float4 v = *(const float4*)&col[ii * 4];
        acc += EXPF(v.x - mx) + EXPF(v.y - mx) + EXPF(v.z - mx) + EXPF(v.w - mx);
    }
    red[tid] = acc;
    __syncthreads();
    for (int s = 512; s > 0; s >>= 1) {
        if (tid < s) red[tid] += red[tid + s];
        __syncthreads();
    }
    const float sum = red[0];
    if (tid == 0) { g_max[e] = mx; g_sum[e] = sum; }
    __syncthreads();

#pragma unroll
    for (int pass = 0; pass < 4; pass++) {
        const int shift = 24 - 8 * pass;
        const uint32_t maskhi = (pass == 0) ? 0u : (0xFFFFFFFFu << (shift + 8));
        if (tid < 256) hist[tid] = 0u;
        __syncthreads();
        const uint32_t pfx = s_prefix;
        for (int i = tid; i < T_TOK; i += 1024) {
            uint32_t key = keys[i];
            if ((key & maskhi) == pfx)
                atomicAdd(&hist[(key >> shift) & 0xFFu], 1u);
        }
        __syncthreads();
        if (tid == 0) {
            uint32_t cum = 0;
            for (int bin = 255; bin >= 0; bin--) {
                uint32_t c = hist[bin];
                if (cum + c >= s_K) {
                    s_K -= cum;
                    s_prefix |= ((uint32_t)bin) << shift;
                    break;
                }
                cum += c;
            }
        }
        __syncthreads();
    }
    const uint32_t V = s_prefix;

    for (int i = tid; i < T_TOK; i += 1024) {
        uint32_t key = keys[i];
        if (key >= V) {
            uint32_t u = (key & 0x80000000u) ? (key ^ 0x80000000u) : ~key;
            float p = __fdiv_rn(EXPF(__uint_as_float(u) - mx), sum);
            uint32_t pos = atomicAdd(&s_cnt, 1u);
            if (pos < CAND)
                cand[pos] = ((u64)__float_as_uint(p) << 32) |
                            (uint32_t)(~((uint32_t)i));
        }
    }
    __syncthreads();
    uint32_t n = s_cnt < CAND ? s_cnt : CAND;
    for (int i = tid; i < CAND; i += 1024)
        if ((uint32_t)i >= n) cand[i] = 0ull;
    __syncthreads();

    for (int ksz = 2; ksz <= CAND; ksz <<= 1) {
        for (int j = ksz >> 1; j > 0; j >>= 1) {
            for (int i = tid; i < CAND; i += 1024) {
                int ixj = i ^ j;
                if (ixj > i) {
                    u64 a = cand[i];
                    u64 c = cand[ixj];
                    bool up = ((i & ksz) == 0);
                    if ((a < c) == up) { cand[i] = c; cand[ixj] = a; }
                }
            }
            __syncthreads();
        }
    }

    {
        u64 c = cand[tid];
        out_vals[(size_t)e * CAP + tid] = __uint_as_float((uint32_t)(c >> 32));
        out_idx [(size_t)e * CAP + tid] = (float)(~((uint32_t)(c & 0xFFFFFFFFull)));
    }
}

// ---------------------------------------------------------------------------
// Kernel 3: probs, float4 vectorized
// ---------------------------------------------------------------------------
__global__ __launch_bounds__(256) void probs_kernel(
    const float* __restrict__ logits, float* __restrict__ probs)
{
    const int i4 = (blockIdx.x * 256 + threadIdx.x) * 4;
    const int e0 = i4 & (N_EXP - 1);
    float4 v = *(const float4*)&logits[i4];
    float4 r;
    r.x = __fdiv_rn(EXPF(v.x - g_max[e0 + 0]), g_sum[e0 + 0]);
    r.y = __fdiv_rn(EXPF(v.y - g_max[e0 + 1]), g_sum[e0 + 1]);
    r.z = __fdiv_rn(EXPF(v.z - g_max[e0 + 2]), g_sum[e0 + 2]);
    r.w = __fdiv_rn(EXPF(v.w - g_max[e0 + 3]), g_sum[e0 + 3]);
    *(float4*)&probs[i4] = r;
}

// ---------------------------------------------------------------------------
extern "C" void kernel_launch(void* const* d_in, const int* in_sizes, int n_in,
                              void* d_out, int out_size)
{
    const float* x = (const float*)d_in[0];
    const float* W = (const float*)d_in[1];
    const float* b = (const float*)d_in[2];

    float* out    = (float*)d_out;
    float* logits = out;
    float* probs  = out + (size_t)T_TOK * N_EXP;
    float* evals  = out + 2 * (size_t)T_TOK * N_EXP;
    float* eidx   = evals + (size_t)N_EXP * CAP;

    size_t topk_smem = (size_t)T_TOK * 4 + (size_t)CAND * 8;
    cudaFuncSetAttribute(topk_kernel,
                         cudaFuncAttributeMaxDynamicSharedMemorySize,
                         (int)topk_smem);

    gemm_kernel<<<T_TOK / BM, 128>>>(x, W, b, logits);
    topk_kernel<<<N_EXP, 1024, topk_smem>>>(evals, eidx);
    probs_kernel<<<(T_TOK * N_EXP) / (256 * 4), 256>>>(logits, probs);
}